// round 4
// baseline (speedup 1.0000x reference)
#include <cuda_runtime.h>
#include <math.h>

// ---------------- problem constants ----------------
#define BATCH   16
#define CDIM    512
#define HWDIM   1024            // H*W = 32*32
#define NGROUPS 32
#define CPG     (CDIM / NGROUPS)   // 16 channels per group
#define NH      8
#define DH      64                  // head dim
#define C3      (3 * CDIM)          // 1536
#define EPSV    1e-5f

// scale = C ** -0.5 (full dim, per reference)
#define ATTN_SCALE 0.044194173824159216f

// ---------------- scratch (device globals: alloc-free rule) ----------------
__device__ float g_h[BATCH * CDIM * HWDIM];    // groupnorm output   (B, C, HW)   32 MiB
__device__ float g_qkv[BATCH * C3 * HWDIM];    // qkv projection     (B, 3C, HW)  96 MiB
__device__ float g_ao[BATCH * CDIM * HWDIM];   // attn out, scrambled(B, C, HW)   32 MiB

// ============================================================
// 1) GroupNorm: one block per (batch, group). 16 ch * 1024 = 16384 elems.
// ============================================================
__global__ __launch_bounds__(256)
void groupnorm_kernel(const float* __restrict__ x,
                      const float* __restrict__ gamma,
                      const float* __restrict__ beta)
{
    const int bg = blockIdx.x;                 // 0..511
    const int b = bg / NGROUPS, g = bg % NGROUPS;
    const int t = threadIdx.x;                 // 256 threads
    const float* xp = x   + (size_t)(b * CDIM + g * CPG) * HWDIM;
    float*       hp = g_h + (size_t)(b * CDIM + g * CPG) * HWDIM;

    // 16384 floats = 4096 float4; 256 threads * 16 float4 each.
    float4 v[16];
    float s = 0.f, ss = 0.f;
#pragma unroll
    for (int i = 0; i < 16; i++) {
        v[i] = reinterpret_cast<const float4*>(xp)[i * 256 + t];
        s  += v[i].x + v[i].y + v[i].z + v[i].w;
        ss += v[i].x * v[i].x + v[i].y * v[i].y + v[i].z * v[i].z + v[i].w * v[i].w;
    }
#pragma unroll
    for (int m = 16; m > 0; m >>= 1) {
        s  += __shfl_xor_sync(0xffffffffu, s,  m);
        ss += __shfl_xor_sync(0xffffffffu, ss, m);
    }
    __shared__ float rs[8], rss[8];
    if ((t & 31) == 0) { rs[t >> 5] = s; rss[t >> 5] = ss; }
    __syncthreads();
    float tot = 0.f, tots = 0.f;
#pragma unroll
    for (int i = 0; i < 8; i++) { tot += rs[i]; tots += rss[i]; }

    const float invN = 1.0f / (float)(CPG * HWDIM);
    const float mean = tot * invN;
    const float var  = tots * invN - mean * mean;
    const float rstd = rsqrtf(var + EPSV);

    // float4 index i*256+t spans exactly channel i within this group.
#pragma unroll
    for (int i = 0; i < 16; i++) {
        const float ga = gamma[g * CPG + i] * rstd;
        const float be = beta[g * CPG + i];
        float4 o;
        o.x = (v[i].x - mean) * ga + be;
        o.y = (v[i].y - mean) * ga + be;
        o.z = (v[i].z - mean) * ga + be;
        o.w = (v[i].w - mean) * ga + be;
        reinterpret_cast<float4*>(hp)[i * 256 + t] = o;
    }
}

// ============================================================
// 2/4) SGEMM: out[b, m, n] = sum_c A[m, c] * Bmat[b, c, n] (+ bias, + resid)
//   MODE 0: A = w_qkv [1536x512], Bmat = g_h,  out = g_qkv
//   MODE 1: A = w_proj [512x512], Bmat = g_ao, out = d_out, + b_proj + x
//   Tiles: 64x64x16, 256 threads, 4x4 microtile.
// ============================================================
template <int MODE>
__global__ __launch_bounds__(256)
void gemm_kernel(const float* __restrict__ A,
                 const float* __restrict__ bias,
                 const float* __restrict__ resid,
                 float* __restrict__ outp)
{
    constexpr int M = (MODE == 0) ? C3 : CDIM;
    constexpr int K = CDIM;
    const int b  = blockIdx.z;
    const int m0 = blockIdx.y * 64;
    const int n0 = blockIdx.x * 64;

    const float* Bb = ((MODE == 0) ? g_h : g_ao) + (size_t)b * K * HWDIM;
    float* out = (MODE == 0) ? (float*)g_qkv : outp;

    __shared__ float As[16][68];   // [k][m], padded
    __shared__ float Bs[16][64];   // [k][n]

    const int t  = threadIdx.x;
    const int ty = t >> 4, tx = t & 15;

    float acc[4][4] = {};

    for (int k0 = 0; k0 < K; k0 += 16) {
        // A tile: 64 rows x 16 cols
        {
            const int row = t >> 2, seg = t & 3;
            float4 a = *reinterpret_cast<const float4*>(A + (size_t)(m0 + row) * K + k0 + seg * 4);
            As[seg * 4 + 0][row] = a.x;
            As[seg * 4 + 1][row] = a.y;
            As[seg * 4 + 2][row] = a.z;
            As[seg * 4 + 3][row] = a.w;
        }
        // B tile: 16 rows x 64 cols
        {
            const int row = t >> 4, seg = t & 15;
            float4 bv = *reinterpret_cast<const float4*>(Bb + (size_t)(k0 + row) * HWDIM + n0 + seg * 4);
            *reinterpret_cast<float4*>(&Bs[row][seg * 4]) = bv;
        }
        __syncthreads();
#pragma unroll
        for (int kk = 0; kk < 16; kk++) {
            const float4 ra = *reinterpret_cast<const float4*>(&As[kk][ty * 4]);
            const float4 rb = *reinterpret_cast<const float4*>(&Bs[kk][tx * 4]);
            const float a0 = ra.x, a1 = ra.y, a2 = ra.z, a3 = ra.w;
            const float b0 = rb.x, b1 = rb.y, b2 = rb.z, b3 = rb.w;
            acc[0][0] += a0 * b0; acc[0][1] += a0 * b1; acc[0][2] += a0 * b2; acc[0][3] += a0 * b3;
            acc[1][0] += a1 * b0; acc[1][1] += a1 * b1; acc[1][2] += a1 * b2; acc[1][3] += a1 * b3;
            acc[2][0] += a2 * b0; acc[2][1] += a2 * b1; acc[2][2] += a2 * b2; acc[2][3] += a2 * b3;
            acc[3][0] += a3 * b0; acc[3][1] += a3 * b1; acc[3][2] += a3 * b2; acc[3][3] += a3 * b3;
        }
        __syncthreads();
    }

#pragma unroll
    for (int i = 0; i < 4; i++) {
        const int m = m0 + ty * 4 + i;
        const int n = n0 + tx * 4;
        const float bi = bias[m];
        float4 o;
        o.x = acc[i][0] + bi; o.y = acc[i][1] + bi;
        o.z = acc[i][2] + bi; o.w = acc[i][3] + bi;
        if (MODE == 1) {
            const float4 r = *reinterpret_cast<const float4*>(resid + ((size_t)b * M + m) * HWDIM + n);
            o.x += r.x; o.y += r.y; o.z += r.z; o.w += r.w;
        }
        *reinterpret_cast<float4*>(out + ((size_t)b * M + m) * HWDIM + n) = o;
    }
}

// ============================================================
// 3) Flash attention, fp32. grid = (16 q-tiles, 128 bh). 256 threads.
//    Q tile 64x64 resident; loop 16 K/V tiles of 64; online softmax.
//    Output written with the reference's head-major batch scramble.
// ============================================================
#define ATTN_SMEM ((64 * 64 * 2 + 64 * 68 * 2) * 4)   // 67584 B

__global__ __launch_bounds__(256)
void attn_kernel()
{
    extern __shared__ float smem[];
    float (*Qs)[64] = (float(*)[64])(smem);                       // [c][q]
    float (*Ks)[64] = (float(*)[64])(smem + 64 * 64);             // [c][k]
    float (*Vs)[68] = (float(*)[68])(smem + 2 * 64 * 64);         // [k][d]
    float (*Ps)[68] = (float(*)[68])(smem + 2 * 64 * 64 + 64 * 68); // [q][k] / [d][q]

    const int qt = blockIdx.x;         // query tile 0..15
    const int bh = blockIdx.y;         // 0..127 ; bh = b*8 + head
    const int b = bh >> 3, head = bh & 7;
    const int n0 = qt * 64;

    const float* qkv = g_qkv + (size_t)b * C3 * HWDIM;
    const float* Qg = qkv + (size_t)(head * 192)       * HWDIM;
    const float* Kg = qkv + (size_t)(head * 192 + 64)  * HWDIM;
    const float* Vg = qkv + (size_t)(head * 192 + 128) * HWDIM;

    const int t  = threadIdx.x;
    const int ty = t >> 4, tx = t & 15;
    const int r = t >> 2, seg = t & 3;   // tile-load roles: row 0..63, 16-float segment

    // Load Q tile (stays resident): Qs[c][q]
#pragma unroll
    for (int j = 0; j < 4; j++) {
        float4 qv = *reinterpret_cast<const float4*>(Qg + (size_t)r * HWDIM + n0 + seg * 16 + j * 4);
        *reinterpret_cast<float4*>(&Qs[r][seg * 16 + j * 4]) = qv;
    }

    float o[4][4] = {};
    float m_run[4] = {-1e30f, -1e30f, -1e30f, -1e30f};
    float l_run[4] = {};

    for (int kt = 0; kt < 16; kt++) {
        const int k0 = kt * 64;
        // Load K (pre-scaled) as Ks[c][k]; V transposed as Vs[k][d]
#pragma unroll
        for (int j = 0; j < 4; j++) {
            float4 kv = *reinterpret_cast<const float4*>(Kg + (size_t)r * HWDIM + k0 + seg * 16 + j * 4);
            kv.x *= ATTN_SCALE; kv.y *= ATTN_SCALE; kv.z *= ATTN_SCALE; kv.w *= ATTN_SCALE;
            *reinterpret_cast<float4*>(&Ks[r][seg * 16 + j * 4]) = kv;
            float4 vv = *reinterpret_cast<const float4*>(Vg + (size_t)r * HWDIM + k0 + seg * 16 + j * 4);
            Vs[seg * 16 + j * 4 + 0][r] = vv.x;
            Vs[seg * 16 + j * 4 + 1][r] = vv.y;
            Vs[seg * 16 + j * 4 + 2][r] = vv.z;
            Vs[seg * 16 + j * 4 + 3][r] = vv.w;
        }
        __syncthreads();

        // S[q][k] = sum_c Qs[c][q] * Ks[c][k]
        float s_[4][4] = {};
#pragma unroll
        for (int c = 0; c < 64; c++) {
            const float4 ra = *reinterpret_cast<const float4*>(&Qs[c][ty * 4]);
            const float4 rb = *reinterpret_cast<const float4*>(&Ks[c][tx * 4]);
            const float a0 = ra.x, a1 = ra.y, a2 = ra.z, a3 = ra.w;
            const float b0 = rb.x, b1 = rb.y, b2 = rb.z, b3 = rb.w;
            s_[0][0] += a0 * b0; s_[0][1] += a0 * b1; s_[0][2] += a0 * b2; s_[0][3] += a0 * b3;
            s_[1][0] += a1 * b0; s_[1][1] += a1 * b1; s_[1][2] += a1 * b2; s_[1][3] += a1 * b3;
            s_[2][0] += a2 * b0; s_[2][1] += a2 * b1; s_[2][2] += a2 * b2; s_[2][3] += a2 * b3;
            s_[3][0] += a3 * b0; s_[3][1] += a3 * b1; s_[3][2] += a3 * b2; s_[3][3] += a3 * b3;
        }

        // online softmax per q-row (16 tx-lanes share each row; shfl within 16-lane halves)
#pragma unroll
        for (int i = 0; i < 4; i++) {
            float rm = fmaxf(fmaxf(s_[i][0], s_[i][1]), fmaxf(s_[i][2], s_[i][3]));
#pragma unroll
            for (int d = 8; d > 0; d >>= 1)
                rm = fmaxf(rm, __shfl_xor_sync(0xffffffffu, rm, d));
            const float newm  = fmaxf(m_run[i], rm);
            const float alpha = __expf(m_run[i] - newm);
            m_run[i] = newm;
            float rl = 0.f;
#pragma unroll
            for (int j = 0; j < 4; j++) {
                s_[i][j] = __expf(s_[i][j] - newm);
                rl += s_[i][j];
            }
#pragma unroll
            for (int d = 8; d > 0; d >>= 1)
                rl += __shfl_xor_sync(0xffffffffu, rl, d);
            l_run[i] = l_run[i] * alpha + rl;
#pragma unroll
            for (int j = 0; j < 4; j++) o[i][j] *= alpha;
            // P -> shared, natural [q][k] layout
            float4 pv; pv.x = s_[i][0]; pv.y = s_[i][1]; pv.z = s_[i][2]; pv.w = s_[i][3];
            *reinterpret_cast<float4*>(&Ps[ty * 4 + i][tx * 4]) = pv;
        }
        __syncthreads();

        // O[q][d] += sum_k Ps[q][k] * Vs[k][d]
#pragma unroll
        for (int k = 0; k < 64; k++) {
            const float4 rv = *reinterpret_cast<const float4*>(&Vs[k][tx * 4]);
            const float p0 = Ps[ty * 4 + 0][k];
            const float p1 = Ps[ty * 4 + 1][k];
            const float p2 = Ps[ty * 4 + 2][k];
            const float p3 = Ps[ty * 4 + 3][k];
            o[0][0] += p0 * rv.x; o[0][1] += p0 * rv.y; o[0][2] += p0 * rv.z; o[0][3] += p0 * rv.w;
            o[1][0] += p1 * rv.x; o[1][1] += p1 * rv.y; o[1][2] += p1 * rv.z; o[1][3] += p1 * rv.w;
            o[2][0] += p2 * rv.x; o[2][1] += p2 * rv.y; o[2][2] += p2 * rv.z; o[2][3] += p2 * rv.w;
            o[3][0] += p3 * rv.x; o[3][1] += p3 * rv.y; o[3][2] += p3 * rv.z; o[3][3] += p3 * rv.w;
        }
        __syncthreads();
    }

    // finalize + stage transposed [d][q] in Ps for coalesced writes
#pragma unroll
    for (int i = 0; i < 4; i++) {
        const float inv_l = 1.0f / l_run[i];
#pragma unroll
        for (int j = 0; j < 4; j++)
            Ps[tx * 4 + j][ty * 4 + i] = o[i][j] * inv_l;
    }
    __syncthreads();

    // Reference scramble: out (B*nh, HW, dh) reshaped as (nh, B, ...) head-major:
    //   b2 = bh % 16, head2 = bh / 16 ; channel = head2*64 + d
    const int b2 = bh & 15, head2 = bh >> 4;
    float* aop = g_ao + ((size_t)b2 * CDIM + head2 * DH) * HWDIM + n0;
#pragma unroll
    for (int j = 0; j < 4; j++) {
        *reinterpret_cast<float4*>(aop + (size_t)r * HWDIM + seg * 16 + j * 4) =
            *reinterpret_cast<const float4*>(&Ps[r][seg * 16 + j * 4]);
    }
}

// ============================================================
// launcher
// ============================================================
extern "C" void kernel_launch(void* const* d_in, const int* in_sizes, int n_in,
                              void* d_out, int out_size)
{
    const float* x      = (const float*)d_in[0];
    const float* gamma  = (const float*)d_in[1];
    const float* beta   = (const float*)d_in[2];
    const float* w_qkv  = (const float*)d_in[3];
    const float* b_qkv  = (const float*)d_in[4];
    const float* w_proj = (const float*)d_in[5];
    const float* b_proj = (const float*)d_in[6];
    float* out = (float*)d_out;

    cudaFuncSetAttribute(attn_kernel, cudaFuncAttributeMaxDynamicSharedMemorySize, ATTN_SMEM);

    // 1) GroupNorm
    groupnorm_kernel<<<BATCH * NGROUPS, 256>>>(x, gamma, beta);

    // 2) QKV GEMM: (1536 x 1024 x 512) per batch
    {
        dim3 grid(HWDIM / 64, C3 / 64, BATCH);
        gemm_kernel<0><<<grid, 256>>>(w_qkv, b_qkv, nullptr, nullptr);
    }

    // 3) Attention
    {
        dim3 grid(HWDIM / 64, BATCH * NH);
        attn_kernel<<<grid, 256, ATTN_SMEM>>>();
    }

    // 4) Proj GEMM + bias + residual
    {
        dim3 grid(HWDIM / 64, CDIM / 64, BATCH);
        gemm_kernel<1><<<grid, 256>>>(w_proj, b_proj, x, out);
    }
}